// round 8
// baseline (speedup 1.0000x reference)
#include <cuda_runtime.h>
#include <cstdint>
#include <cmath>

#define T_SEQ   4096
#define TAGS    24
#define START_T 22
#define STOP_T  23
#define NEGV    (-10000.0f)

#define NCTA_DIR    64
#define REC_THREADS 256

// ---------------- scratch (device globals; no cudaMalloc allowed) ----------
__device__ float    g_xg[(size_t)T_SEQ * 4096];   // [t][dir*2048 + gate*512 + cell]
__device__ float    g_lstm[(size_t)T_SEQ * 1024]; // [t][dir*512 + cell]
__device__ float    g_feats[T_SEQ * TAGS];
__device__ float    g_h[2][2][512];               // [dir][parity][cell]
__device__ unsigned g_cnt[64];                    // [d*32] : 128B-separated counters

__device__ __forceinline__ unsigned ld_acq(const unsigned* p)
{
    unsigned v;
    asm volatile("ld.acquire.gpu.global.u32 %0, [%1];" : "=r"(v) : "l"(p) : "memory");
    return v;
}
__device__ __forceinline__ void red_rel(unsigned* p)
{
    asm volatile("red.release.gpu.global.add.u32 [%0], %1;" :: "l"(p), "r"(1u) : "memory");
}

// ---------------- kernel 1: fused gather + input-projection GEMM -----------
__global__ void proj_gemm(const int* __restrict__ sent, const float* __restrict__ emb,
                          const float* __restrict__ wf, const float* __restrict__ wb,
                          const float* __restrict__ bihf, const float* __restrict__ bhhf,
                          const float* __restrict__ bihb, const float* __restrict__ bhhb)
{
    __shared__ __align__(16) float As[32][68];
    __shared__ __align__(16) float Bs[32][68];
    __shared__ int toks[64];

    const int tid = threadIdx.x;          // 0..255
    const int m0 = blockIdx.y * 64;
    const int n0 = blockIdx.x * 64;
    if (tid < 64) toks[tid] = sent[m0 + tid];
    __syncthreads();

    const int ty = tid >> 4;              // 0..15
    const int tx = tid & 15;              // 0..15

    float acc[4][4];
#pragma unroll
    for (int i = 0; i < 4; i++)
#pragma unroll
        for (int j = 0; j < 4; j++) acc[i][j] = 0.f;

    for (int k0 = 0; k0 < 512; k0 += 32) {
#pragma unroll
        for (int r = 0; r < 2; r++) {
            int idx = tid + r * 256;
            int row = idx >> 3;
            int kq  = idx & 7;
            float4 a = *(const float4*)(emb + (size_t)toks[row] * 512 + k0 + kq * 4);
            As[kq*4+0][row] = a.x; As[kq*4+1][row] = a.y;
            As[kq*4+2][row] = a.z; As[kq*4+3][row] = a.w;
            int n = n0 + row;
            const float* wsrc = (n < 2048) ? (wf + (size_t)n * 512)
                                           : (wb + (size_t)(n - 2048) * 512);
            float4 b = *(const float4*)(wsrc + k0 + kq * 4);
            Bs[kq*4+0][row] = b.x; Bs[kq*4+1][row] = b.y;
            Bs[kq*4+2][row] = b.z; Bs[kq*4+3][row] = b.w;
        }
        __syncthreads();
#pragma unroll
        for (int kk = 0; kk < 32; kk++) {
            float4 aa = *(const float4*)&As[kk][ty * 4];
            float4 bb = *(const float4*)&Bs[kk][tx * 4];
            float av[4] = {aa.x, aa.y, aa.z, aa.w};
            float bv[4] = {bb.x, bb.y, bb.z, bb.w};
#pragma unroll
            for (int i = 0; i < 4; i++)
#pragma unroll
                for (int j = 0; j < 4; j++) acc[i][j] += av[i] * bv[j];
        }
        __syncthreads();
    }

#pragma unroll
    for (int i = 0; i < 4; i++) {
        int m = m0 + ty * 4 + i;
        float* orow = g_xg + (size_t)m * 4096 + n0 + tx * 4;
#pragma unroll
        for (int j = 0; j < 4; j++) {
            int n = n0 + tx * 4 + j;
            float bias = (n < 2048) ? (bihf[n] + bhhf[n])
                                    : (bihb[n - 2048] + bhhb[n - 2048]);
            orow[j] = acc[i][j] + bias;
        }
    }
}

// ---------------- kernel 2: persistent BiLSTM recurrence -------------------
// 128 CTAs (64/dir), 256 threads. Thread (w=tid>>5, l=tid&31):
//   row = (l>>3)*512 + 8r + (l&7), k-slice [64w, 64w+64), weights in REGISTERS.
// h published per step via one-sided counter (red.release / ld.acquire).
__global__ void __launch_bounds__(REC_THREADS, 1)
lstm_rec(const float* __restrict__ whf, const float* __restrict__ whb,
         const float* __restrict__ h0, const float* __restrict__ c0)
{
    const int cta = blockIdx.x;       // 0..127
    const int d   = cta >> 6;
    const int r   = cta & 63;         // cells [8r, 8r+8)
    const int tid = threadIdx.x;
    const int w   = tid >> 5;         // 0..7 k-slice (warp-uniform)
    const int l   = tid & 31;         // 0..31 local gate-row
    const int gate = l >> 3;
    const int cell = (r << 3) + (l & 7);
    const int row  = gate * 512 + cell;

    const float* whh = d ? whb : whf;
    unsigned* cnt = &g_cnt[d * 32];

    // ---- weights -> registers (one-time) ----
    float4 W[16];
    {
        const float4* wp = (const float4*)(whh + (size_t)row * 512 + w * 64);
#pragma unroll
        for (int i = 0; i < 16; i++) W[i] = wp[i];
    }

    __shared__ __align__(16) float sg[8][33];   // [w][l] partials, padded

    float cst = 0.f;
    if (tid < 8) {
        cst = c0[d * 512 + (r << 3) + tid];
        __stcg(&g_h[d][0][(r << 3) + tid], h0[d * 512 + (r << 3) + tid]);
    }
    __syncthreads();
    if (tid == 0) red_rel(cnt);       // publication p=0 (h0)

    unsigned target = NCTA_DIR;
    for (int s = 0; s < T_SEQ; s++) {
        const int t = d ? (T_SEQ - 1 - s) : s;

        // prefetch xg for the reducer lanes (independent of h)
        float xv = 0.f;
        if (tid < 32) xv = __ldcg(&g_xg[(size_t)t * 4096 + d * 2048 + row]);

        if (tid == 0) {
            while (ld_acq(cnt) < target) { }
        }
        __syncthreads();

        // h vector (lane-invariant addresses -> broadcast wavefronts), L2 path
        const float4* hb = (const float4*)(&g_h[d][s & 1][0]) + w * 16;
        float4 acc = {0.f, 0.f, 0.f, 0.f};
#pragma unroll
        for (int i = 0; i < 16; i++) {
            float4 h = __ldcg(hb + i);
            acc.x += W[i].x * h.x; acc.y += W[i].y * h.y;
            acc.z += W[i].z * h.z; acc.w += W[i].w * h.w;
        }
        sg[w][l] = (acc.x + acc.y) + (acc.z + acc.w);
        __syncthreads();

        if (tid < 32) {   // warp 0 reduces + gates
            float a = ((sg[0][l] + sg[1][l]) + (sg[2][l] + sg[3][l]))
                    + ((sg[4][l] + sg[5][l]) + (sg[6][l] + sg[7][l]));
            a += xv;
            float fg = __shfl_sync(0xffffffffu, a, (l & 7) + 8);
            float gg = __shfl_sync(0xffffffffu, a, (l & 7) + 16);
            float ov = __shfl_sync(0xffffffffu, a, (l & 7) + 24);
            if (l < 8) {
                float iv = 1.f / (1.f + expf(-a));
                fg = 1.f / (1.f + expf(-fg));
                gg = tanhf(gg);
                ov = 1.f / (1.f + expf(-ov));
                cst = fg * cst + iv * gg;
                float hn = ov * tanhf(cst);
                __stcg(&g_h[d][(s + 1) & 1][(r << 3) + l], hn);
                __stcg(&g_lstm[(size_t)t * 1024 + d * 512 + (r << 3) + l], hn);
            }
        }
        __syncthreads();
        if (tid == 0) red_rel(cnt);   // publication p=s+1
        target += NCTA_DIR;
    }

    // self-reset for graph replay: wait for all publications, then zero.
    if (r == 0 && tid == 0) {
        const unsigned done = (unsigned)NCTA_DIR * (T_SEQ + 1);
        while (ld_acq(cnt) < done) { }
        atomicExch(cnt, 0u);
    }
}

// ---------------- kernel 3: tag features -----------------------------------
__global__ void feats_k(const float* __restrict__ wtag, const float* __restrict__ btag)
{
    const int t = blockIdx.x;
    const int w = threadIdx.x >> 5;
    const int lane = threadIdx.x & 31;

    const float4* lx = (const float4*)(g_lstm + (size_t)t * 1024 + lane * 32);
    float4 X[8];
#pragma unroll
    for (int i = 0; i < 8; i++) X[i] = lx[i];

#pragma unroll
    for (int rep = 0; rep < 3; rep++) {
        int tag = w + rep * 8;
        const float4* wt = (const float4*)(wtag + (size_t)tag * 1024 + lane * 32);
        float a = 0.f;
#pragma unroll
        for (int i = 0; i < 8; i++) {
            float4 v = wt[i];
            a += X[i].x * v.x + X[i].y * v.y + X[i].z * v.z + X[i].w * v.w;
        }
#pragma unroll
        for (int o = 16; o; o >>= 1) a += __shfl_xor_sync(0xffffffffu, a, o);
        if (lane == 0) g_feats[t * TAGS + tag] = a + btag[tag];
    }
}

// ---------------- kernel 4: Viterbi (1 warp, bp in smem) -------------------
__global__ void viterbi_k(const float* __restrict__ trans, float* __restrict__ out,
                          int out_size)
{
    extern __shared__ unsigned char bp[];      // T_SEQ * TAGS bytes
    __shared__ float trs[TAGS * 25];
    __shared__ float stopr[TAGS];

    const int lane = threadIdx.x;
    for (int i = lane; i < TAGS * TAGS; i += 32) {
        int n = i / TAGS, p = i % TAGS;
        trs[n * 25 + p] = trans[i];
    }
    if (lane < TAGS) stopr[lane] = trans[STOP_T * TAGS + lane];
    __syncwarp();

    float fv = (lane == START_T) ? 0.f : NEGV;
    float feat = (lane < TAGS) ? g_feats[lane] : 0.f;

    for (int t = 0; t < T_SEQ; t++) {
        float nf = (lane < TAGS && t + 1 < T_SEQ) ? g_feats[(t + 1) * TAGS + lane] : 0.f;
        float best = -3.4e38f;
        int bi = 0;
#pragma unroll
        for (int p = 0; p < TAGS; p++) {
            float src = __shfl_sync(0xffffffffu, fv, p);
            float v = src + ((lane < TAGS) ? trs[lane * 25 + p] : 0.f);
            if (v > best) { best = v; bi = p; }
        }
        if (lane < TAGS) {
            fv = best + feat;
            bp[t * TAGS + lane] = (unsigned char)bi;
        } else {
            fv = NEGV;
        }
        feat = nf;
    }

    float ttl = (lane < TAGS) ? fv + stopr[lane] : -3.4e38f;
    float bv = ttl; int bi = lane;
#pragma unroll
    for (int o = 16; o; o >>= 1) {
        float ov = __shfl_down_sync(0xffffffffu, bv, o);
        int   oi = __shfl_down_sync(0xffffffffu, bi, o);
        if (ov > bv || (ov == bv && oi < bi)) { bv = ov; bi = oi; }
    }

    if (lane == 0) {
        float score = bv;
        int cur = bi;
        if (out_size >= T_SEQ + 1) {
            out[0] = score;
            float* path = out + 1;
            path[T_SEQ - 1] = (float)cur;
            for (int t = T_SEQ - 1; t >= 1; t--) {
                cur = bp[t * TAGS + cur];
                path[t - 1] = (float)cur;
            }
        } else if (out_size == T_SEQ) {
            out[T_SEQ - 1] = (float)cur;
            for (int t = T_SEQ - 1; t >= 1; t--) {
                cur = bp[t * TAGS + cur];
                out[t - 1] = (float)cur;
            }
        } else {
            out[0] = score;
        }
    }
}

// ---------------- launcher --------------------------------------------------
extern "C" void kernel_launch(void* const* d_in, const int* in_sizes, int n_in,
                              void* d_out, int out_size)
{
    const int*   sent  = (const int*)  d_in[0];
    const float* emb   = (const float*)d_in[1];
    const float* wihf  = (const float*)d_in[2];
    const float* whhf  = (const float*)d_in[3];
    const float* bihf  = (const float*)d_in[4];
    const float* bhhf  = (const float*)d_in[5];
    const float* wihb  = (const float*)d_in[6];
    const float* whhb  = (const float*)d_in[7];
    const float* bihb  = (const float*)d_in[8];
    const float* bhhb  = (const float*)d_in[9];
    const float* wtag  = (const float*)d_in[10];
    const float* btag  = (const float*)d_in[11];
    const float* trans = (const float*)d_in[12];
    const float* h0    = (const float*)d_in[13];
    const float* c0    = (const float*)d_in[14];
    float* out = (float*)d_out;

    proj_gemm<<<dim3(64, 64), 256>>>(sent, emb, wihf, wihb, bihf, bhhf, bihb, bhhb);
    lstm_rec<<<2 * NCTA_DIR, REC_THREADS>>>(whhf, whhb, h0, c0);
    feats_k<<<T_SEQ, 256>>>(wtag, btag);

    cudaFuncSetAttribute(viterbi_k, cudaFuncAttributeMaxDynamicSharedMemorySize,
                         T_SEQ * TAGS);
    viterbi_k<<<1, 32, T_SEQ * TAGS>>>(trans, out, out_size);
}

// round 9
// speedup vs baseline: 1.1055x; 1.1055x over previous
#include <cuda_runtime.h>
#include <cstdint>
#include <cmath>

#define T_SEQ   4096
#define TAGS    24
#define START_T 22
#define STOP_T  23
#define NEGV    (-10000.0f)

#define NCTA_DIR    64
#define REC_THREADS 256

// ---------------- scratch (device globals; no cudaMalloc allowed) ----------
__device__ float    g_xg[(size_t)T_SEQ * 4096];   // [t][dir*2048 + gate*512 + cell]
__device__ float    g_lstm[(size_t)T_SEQ * 1024]; // [t][dir*512 + cell]
__device__ float    g_feats[T_SEQ * TAGS];
__device__ float    g_h[2][2][512];               // [dir][parity][cell]
__device__ unsigned g_cnt[64];                    // [d*32] : 128B-separated counters

__device__ __forceinline__ unsigned ld_acq(const unsigned* p)
{
    unsigned v;
    asm volatile("ld.acquire.gpu.global.u32 %0, [%1];" : "=r"(v) : "l"(p) : "memory");
    return v;
}
__device__ __forceinline__ void red_rel(unsigned* p)
{
    asm volatile("red.release.gpu.global.add.u32 [%0], %1;" :: "l"(p), "r"(1u) : "memory");
}

// ---------------- kernel 1: fused gather + input-projection GEMM -----------
__global__ void proj_gemm(const int* __restrict__ sent, const float* __restrict__ emb,
                          const float* __restrict__ wf, const float* __restrict__ wb,
                          const float* __restrict__ bihf, const float* __restrict__ bhhf,
                          const float* __restrict__ bihb, const float* __restrict__ bhhb)
{
    __shared__ __align__(16) float As[32][68];
    __shared__ __align__(16) float Bs[32][68];
    __shared__ int toks[64];

    const int tid = threadIdx.x;          // 0..255
    const int m0 = blockIdx.y * 64;
    const int n0 = blockIdx.x * 64;
    if (tid < 64) toks[tid] = sent[m0 + tid];
    __syncthreads();

    const int ty = tid >> 4;              // 0..15
    const int tx = tid & 15;              // 0..15

    float acc[4][4];
#pragma unroll
    for (int i = 0; i < 4; i++)
#pragma unroll
        for (int j = 0; j < 4; j++) acc[i][j] = 0.f;

    for (int k0 = 0; k0 < 512; k0 += 32) {
#pragma unroll
        for (int r = 0; r < 2; r++) {
            int idx = tid + r * 256;
            int row = idx >> 3;
            int kq  = idx & 7;
            float4 a = *(const float4*)(emb + (size_t)toks[row] * 512 + k0 + kq * 4);
            As[kq*4+0][row] = a.x; As[kq*4+1][row] = a.y;
            As[kq*4+2][row] = a.z; As[kq*4+3][row] = a.w;
            int n = n0 + row;
            const float* wsrc = (n < 2048) ? (wf + (size_t)n * 512)
                                           : (wb + (size_t)(n - 2048) * 512);
            float4 b = *(const float4*)(wsrc + k0 + kq * 4);
            Bs[kq*4+0][row] = b.x; Bs[kq*4+1][row] = b.y;
            Bs[kq*4+2][row] = b.z; Bs[kq*4+3][row] = b.w;
        }
        __syncthreads();
#pragma unroll
        for (int kk = 0; kk < 32; kk++) {
            float4 aa = *(const float4*)&As[kk][ty * 4];
            float4 bb = *(const float4*)&Bs[kk][tx * 4];
            float av[4] = {aa.x, aa.y, aa.z, aa.w};
            float bv[4] = {bb.x, bb.y, bb.z, bb.w};
#pragma unroll
            for (int i = 0; i < 4; i++)
#pragma unroll
                for (int j = 0; j < 4; j++) acc[i][j] += av[i] * bv[j];
        }
        __syncthreads();
    }

#pragma unroll
    for (int i = 0; i < 4; i++) {
        int m = m0 + ty * 4 + i;
        float* orow = g_xg + (size_t)m * 4096 + n0 + tx * 4;
#pragma unroll
        for (int j = 0; j < 4; j++) {
            int n = n0 + tx * 4 + j;
            float bias = (n < 2048) ? (bihf[n] + bhhf[n])
                                    : (bihb[n - 2048] + bhhb[n - 2048]);
            orow[j] = acc[i][j] + bias;
        }
    }
}

// ---------------- kernel 2: persistent BiLSTM recurrence -------------------
// 128 CTAs (64/dir), 256 threads. Thread (w=tid>>5, l=tid&31):
//   row = (l>>3)*512 + 8r + (l&7), k-slice [64w, 64w+64), weights in REGISTERS.
// h published per step via one-sided counter (red.release / ld.acquire).
__global__ void __launch_bounds__(REC_THREADS, 1)
lstm_rec(const float* __restrict__ whf, const float* __restrict__ whb,
         const float* __restrict__ h0, const float* __restrict__ c0)
{
    const int cta = blockIdx.x;       // 0..127
    const int d   = cta >> 6;
    const int r   = cta & 63;         // cells [8r, 8r+8)
    const int tid = threadIdx.x;
    const int w   = tid >> 5;         // 0..7 k-slice (warp-uniform)
    const int l   = tid & 31;         // 0..31 local gate-row
    const int gate = l >> 3;
    const int cell = (r << 3) + (l & 7);
    const int row  = gate * 512 + cell;

    const float* whh = d ? whb : whf;
    unsigned* cnt = &g_cnt[d * 32];

    // ---- weights -> registers (one-time) ----
    float4 W[16];
    {
        const float4* wp = (const float4*)(whh + (size_t)row * 512 + w * 64);
#pragma unroll
        for (int i = 0; i < 16; i++) W[i] = wp[i];
    }

    __shared__ __align__(16) float sg[8][33];   // [w][l] partials, padded

    float cst = 0.f;
    if (tid < 8) {
        cst = c0[d * 512 + (r << 3) + tid];
        __stcg(&g_h[d][0][(r << 3) + tid], h0[d * 512 + (r << 3) + tid]);
    }
    __syncthreads();
    if (tid == 0) red_rel(cnt);       // publication p=0 (h0)

    unsigned target = NCTA_DIR;
    for (int s = 0; s < T_SEQ; s++) {
        const int t = d ? (T_SEQ - 1 - s) : s;

        // prefetch xg for the reducer lanes (independent of h)
        float xv = 0.f;
        if (tid < 32) xv = __ldcg(&g_xg[(size_t)t * 4096 + d * 2048 + row]);

        if (tid == 0) {
            while (ld_acq(cnt) < target) { }
        }
        __syncthreads();

        // h vector (lane-invariant addresses -> broadcast wavefronts), L2 path
        const float4* hb = (const float4*)(&g_h[d][s & 1][0]) + w * 16;
        float4 acc = {0.f, 0.f, 0.f, 0.f};
#pragma unroll
        for (int i = 0; i < 16; i++) {
            float4 h = __ldcg(hb + i);
            acc.x += W[i].x * h.x; acc.y += W[i].y * h.y;
            acc.z += W[i].z * h.z; acc.w += W[i].w * h.w;
        }
        sg[w][l] = (acc.x + acc.y) + (acc.z + acc.w);
        __syncthreads();

        if (tid < 32) {   // warp 0 reduces + gates
            float a = ((sg[0][l] + sg[1][l]) + (sg[2][l] + sg[3][l]))
                    + ((sg[4][l] + sg[5][l]) + (sg[6][l] + sg[7][l]));
            a += xv;
            float fg = __shfl_sync(0xffffffffu, a, (l & 7) + 8);
            float gg = __shfl_sync(0xffffffffu, a, (l & 7) + 16);
            float ov = __shfl_sync(0xffffffffu, a, (l & 7) + 24);
            if (l < 8) {
                float iv = 1.f / (1.f + expf(-a));
                fg = 1.f / (1.f + expf(-fg));
                gg = tanhf(gg);
                ov = 1.f / (1.f + expf(-ov));
                cst = fg * cst + iv * gg;
                float hn = ov * tanhf(cst);
                __stcg(&g_h[d][(s + 1) & 1][(r << 3) + l], hn);
                __stcg(&g_lstm[(size_t)t * 1024 + d * 512 + (r << 3) + l], hn);
            }
        }
        __syncthreads();
        if (tid == 0) red_rel(cnt);   // publication p=s+1
        target += NCTA_DIR;
    }

    // self-reset for graph replay: wait for all publications, then zero.
    if (r == 0 && tid == 0) {
        const unsigned done = (unsigned)NCTA_DIR * (T_SEQ + 1);
        while (ld_acq(cnt) < done) { }
        atomicExch(cnt, 0u);
    }
}

// ---------------- kernel 3: tag features -----------------------------------
__global__ void feats_k(const float* __restrict__ wtag, const float* __restrict__ btag)
{
    const int t = blockIdx.x;
    const int w = threadIdx.x >> 5;
    const int lane = threadIdx.x & 31;

    const float4* lx = (const float4*)(g_lstm + (size_t)t * 1024 + lane * 32);
    float4 X[8];
#pragma unroll
    for (int i = 0; i < 8; i++) X[i] = lx[i];

#pragma unroll
    for (int rep = 0; rep < 3; rep++) {
        int tag = w + rep * 8;
        const float4* wt = (const float4*)(wtag + (size_t)tag * 1024 + lane * 32);
        float a = 0.f;
#pragma unroll
        for (int i = 0; i < 8; i++) {
            float4 v = wt[i];
            a += X[i].x * v.x + X[i].y * v.y + X[i].z * v.z + X[i].w * v.w;
        }
#pragma unroll
        for (int o = 16; o; o >>= 1) a += __shfl_xor_sync(0xffffffffu, a, o);
        if (lane == 0) g_feats[t * TAGS + tag] = a + btag[tag];
    }
}

// ---------------- kernel 4: Viterbi (1 warp, bp in smem) -------------------
__global__ void viterbi_k(const float* __restrict__ trans, float* __restrict__ out,
                          int out_size)
{
    extern __shared__ unsigned char bp[];      // T_SEQ * TAGS bytes
    __shared__ float trs[TAGS * 25];
    __shared__ float stopr[TAGS];

    const int lane = threadIdx.x;
    for (int i = lane; i < TAGS * TAGS; i += 32) {
        int n = i / TAGS, p = i % TAGS;
        trs[n * 25 + p] = trans[i];
    }
    if (lane < TAGS) stopr[lane] = trans[STOP_T * TAGS + lane];
    __syncwarp();

    float fv = (lane == START_T) ? 0.f : NEGV;
    float feat = (lane < TAGS) ? g_feats[lane] : 0.f;

    for (int t = 0; t < T_SEQ; t++) {
        float nf = (lane < TAGS && t + 1 < T_SEQ) ? g_feats[(t + 1) * TAGS + lane] : 0.f;
        float best = -3.4e38f;
        int bi = 0;
#pragma unroll
        for (int p = 0; p < TAGS; p++) {
            float src = __shfl_sync(0xffffffffu, fv, p);
            float v = src + ((lane < TAGS) ? trs[lane * 25 + p] : 0.f);
            if (v > best) { best = v; bi = p; }
        }
        if (lane < TAGS) {
            fv = best + feat;
            bp[t * TAGS + lane] = (unsigned char)bi;
        } else {
            fv = NEGV;
        }
        feat = nf;
    }

    float ttl = (lane < TAGS) ? fv + stopr[lane] : -3.4e38f;
    float bv = ttl; int bi = lane;
#pragma unroll
    for (int o = 16; o; o >>= 1) {
        float ov = __shfl_down_sync(0xffffffffu, bv, o);
        int   oi = __shfl_down_sync(0xffffffffu, bi, o);
        if (ov > bv || (ov == bv && oi < bi)) { bv = ov; bi = oi; }
    }

    if (lane == 0) {
        float score = bv;
        int cur = bi;
        if (out_size >= T_SEQ + 1) {
            out[0] = score;
            float* path = out + 1;
            path[T_SEQ - 1] = (float)cur;
            for (int t = T_SEQ - 1; t >= 1; t--) {
                cur = bp[t * TAGS + cur];
                path[t - 1] = (float)cur;
            }
        } else if (out_size == T_SEQ) {
            out[T_SEQ - 1] = (float)cur;
            for (int t = T_SEQ - 1; t >= 1; t--) {
                cur = bp[t * TAGS + cur];
                out[t - 1] = (float)cur;
            }
        } else {
            out[0] = score;
        }
    }
}

// ---------------- launcher --------------------------------------------------
extern "C" void kernel_launch(void* const* d_in, const int* in_sizes, int n_in,
                              void* d_out, int out_size)
{
    const int*   sent  = (const int*)  d_in[0];
    const float* emb   = (const float*)d_in[1];
    const float* wihf  = (const float*)d_in[2];
    const float* whhf  = (const float*)d_in[3];
    const float* bihf  = (const float*)d_in[4];
    const float* bhhf  = (const float*)d_in[5];
    const float* wihb  = (const float*)d_in[6];
    const float* whhb  = (const float*)d_in[7];
    const float* bihb  = (const float*)d_in[8];
    const float* bhhb  = (const float*)d_in[9];
    const float* wtag  = (const float*)d_in[10];
    const float* btag  = (const float*)d_in[11];
    const float* trans = (const float*)d_in[12];
    const float* h0    = (const float*)d_in[13];
    const float* c0    = (const float*)d_in[14];
    float* out = (float*)d_out;

    proj_gemm<<<dim3(64, 64), 256>>>(sent, emb, wihf, wihb, bihf, bhhf, bihb, bhhb);
    lstm_rec<<<2 * NCTA_DIR, REC_THREADS>>>(whhf, whhb, h0, c0);
    feats_k<<<T_SEQ, 256>>>(wtag, btag);

    cudaFuncSetAttribute(viterbi_k, cudaFuncAttributeMaxDynamicSharedMemorySize,
                         T_SEQ * TAGS);
    viterbi_k<<<1, 32, T_SEQ * TAGS>>>(trans, out, out_size);
}

// round 10
// speedup vs baseline: 1.3719x; 1.2410x over previous
#include <cuda_runtime.h>
#include <cstdint>
#include <cmath>

#define T_SEQ   4096
#define TAGS    24
#define START_T 22
#define STOP_T  23
#define NEGV    (-10000.0f)

#define NCTA_DIR    64
#define REC_THREADS 256

// ---------------- scratch (device globals; no cudaMalloc allowed) ----------
__device__ float    g_xg[(size_t)T_SEQ * 4096];   // [t][dir*2048 + gate*512 + cell]
__device__ float    g_lstm[(size_t)T_SEQ * 1024]; // [t][dir*512 + cell]
__device__ float    g_feats[T_SEQ * TAGS];
// h exchange: one 8B word per cell = (tag<<32 | fp32 bits). Tag==step+1 for the
// h that is INPUT to step 'step'; double-buffered by step parity.
__device__ unsigned long long g_hx[2][2][512];    // [dir][parity][cell]

__device__ __forceinline__ unsigned long long ld_acq64(const unsigned long long* p)
{
    unsigned long long v;
    asm volatile("ld.acquire.gpu.global.u64 %0, [%1];" : "=l"(v) : "l"(p) : "memory");
    return v;
}
__device__ __forceinline__ void st_rel64(unsigned long long* p, unsigned long long v)
{
    asm volatile("st.release.gpu.global.u64 [%0], %1;" :: "l"(p), "l"(v) : "memory");
}
__device__ __forceinline__ unsigned long long pack_ht(float h, unsigned tag)
{
    return ((unsigned long long)tag << 32) | (unsigned long long)__float_as_uint(h);
}

#define FMA2(d, a, b, c) \
    asm("fma.rn.f32x2 %0, %1, %2, %3;" : "=l"(d) : "l"(a), "l"(b), "l"(c))

// ---------------- kernel 1: fused gather + input-projection GEMM -----------
__global__ void proj_gemm(const int* __restrict__ sent, const float* __restrict__ emb,
                          const float* __restrict__ wf, const float* __restrict__ wb,
                          const float* __restrict__ bihf, const float* __restrict__ bhhf,
                          const float* __restrict__ bihb, const float* __restrict__ bhhb)
{
    __shared__ __align__(16) float As[32][68];
    __shared__ __align__(16) float Bs[32][68];
    __shared__ int toks[64];

    const int tid = threadIdx.x;          // 0..255
    const int m0 = blockIdx.y * 64;
    const int n0 = blockIdx.x * 64;
    if (tid < 64) toks[tid] = sent[m0 + tid];
    __syncthreads();

    const int ty = tid >> 4;
    const int tx = tid & 15;

    float acc[4][4];
#pragma unroll
    for (int i = 0; i < 4; i++)
#pragma unroll
        for (int j = 0; j < 4; j++) acc[i][j] = 0.f;

    for (int k0 = 0; k0 < 512; k0 += 32) {
#pragma unroll
        for (int r = 0; r < 2; r++) {
            int idx = tid + r * 256;
            int row = idx >> 3;
            int kq  = idx & 7;
            float4 a = *(const float4*)(emb + (size_t)toks[row] * 512 + k0 + kq * 4);
            As[kq*4+0][row] = a.x; As[kq*4+1][row] = a.y;
            As[kq*4+2][row] = a.z; As[kq*4+3][row] = a.w;
            int n = n0 + row;
            const float* wsrc = (n < 2048) ? (wf + (size_t)n * 512)
                                           : (wb + (size_t)(n - 2048) * 512);
            float4 b = *(const float4*)(wsrc + k0 + kq * 4);
            Bs[kq*4+0][row] = b.x; Bs[kq*4+1][row] = b.y;
            Bs[kq*4+2][row] = b.z; Bs[kq*4+3][row] = b.w;
        }
        __syncthreads();
#pragma unroll
        for (int kk = 0; kk < 32; kk++) {
            float4 aa = *(const float4*)&As[kk][ty * 4];
            float4 bb = *(const float4*)&Bs[kk][tx * 4];
            float av[4] = {aa.x, aa.y, aa.z, aa.w};
            float bv[4] = {bb.x, bb.y, bb.z, bb.w};
#pragma unroll
            for (int i = 0; i < 4; i++)
#pragma unroll
                for (int j = 0; j < 4; j++) acc[i][j] += av[i] * bv[j];
        }
        __syncthreads();
    }

#pragma unroll
    for (int i = 0; i < 4; i++) {
        int m = m0 + ty * 4 + i;
        float* orow = g_xg + (size_t)m * 4096 + n0 + tx * 4;
#pragma unroll
        for (int j = 0; j < 4; j++) {
            int n = n0 + tx * 4 + j;
            float bias = (n < 2048) ? (bihf[n] + bhhf[n])
                                    : (bihb[n - 2048] + bhhb[n - 2048]);
            orow[j] = acc[i][j] + bias;
        }
    }
}

// ---------------- kernel 2: persistent BiLSTM recurrence -------------------
// 128 CTAs (64/dir), 256 threads. Thread (w=tid>>5, l=tid&31):
//   gate-row = (l>>3)*512 + 8r + (l&7), k-slice [64w, 64w+64), weights packed
//   as f32x2 in REGISTERS. h published per cell as (tag|value) 8B words:
//   the successful acquire-poll IS the data transfer (one L2 round trip).
__global__ void __launch_bounds__(REC_THREADS, 1)
lstm_rec(const float* __restrict__ whf, const float* __restrict__ whb,
         const float* __restrict__ h0, const float* __restrict__ c0)
{
    const int cta = blockIdx.x;       // 0..127
    const int d   = cta >> 6;
    const int r   = cta & 63;         // owns cells [8r, 8r+8)
    const int tid = threadIdx.x;
    const int w   = tid >> 5;         // 0..7 k-slice (warp-uniform)
    const int l   = tid & 31;         // 0..31 local gate-row
    const int gate = l >> 3;
    const int cell = (r << 3) + (l & 7);
    const int row  = gate * 512 + cell;

    const float* whh = d ? whb : whf;

    // ---- weights -> registers, packed f32x2 (one-time) ----
    unsigned long long W2[32];
    {
        const float2* wp = (const float2*)(whh + (size_t)row * 512 + w * 64);
#pragma unroll
        for (int i = 0; i < 32; i++) {
            float2 v = wp[i];
            W2[i] = ((unsigned long long)__float_as_uint(v.y) << 32)
                  | (unsigned long long)__float_as_uint(v.x);
        }
    }

    __shared__ __align__(16) float hsh[8][64];  // per-warp h slice
    __shared__ float sg[8][33];                 // [w][l] partials, padded

    float cst = 0.f;
    if (tid < 8) {
        cst = c0[d * 512 + (r << 3) + tid];
        st_rel64(&g_hx[d][0][(r << 3) + tid],
                 pack_ht(h0[d * 512 + (r << 3) + tid], 1u));
    }

    for (int s = 0; s < T_SEQ; s++) {
        const int t = d ? (T_SEQ - 1 - s) : s;

        // xg prefetch for reducer lanes (independent of h)
        float xv = 0.f;
        if (tid < 32) xv = __ldcg(&g_xg[(size_t)t * 4096 + d * 2048 + row]);

        // ---- poll h (data-embedded tags); poll success == data arrival ----
        const unsigned want = (unsigned)(s + 1);
        const unsigned long long* hb = &g_hx[d][s & 1][w * 64];
        unsigned long long v0 = 0, v1 = 0;
        bool d0 = false, d1 = false;
        for (;;) {
            if (!d0) { v0 = ld_acq64(hb + l);      d0 = ((unsigned)(v0 >> 32) == want); }
            if (!d1) { v1 = ld_acq64(hb + 32 + l); d1 = ((unsigned)(v1 >> 32) == want); }
            if (__all_sync(0xffffffffu, d0 && d1)) break;
        }
        hsh[w][l]      = __uint_as_float((unsigned)v0);
        hsh[w][32 + l] = __uint_as_float((unsigned)v1);
        __syncwarp();

        // ---- dot: packed f32x2 FMA over warp's 64-wide k-slice ----
        const ulonglong2* hv = (const ulonglong2*)&hsh[w][0];  // 16 × 16B, broadcast LDS
        unsigned long long a0 = 0ull, a1 = 0ull;
#pragma unroll
        for (int i = 0; i < 16; i++) {
            ulonglong2 h2 = hv[i];
            FMA2(a0, W2[2 * i],     h2.x, a0);
            FMA2(a1, W2[2 * i + 1], h2.y, a1);
        }
        float p0 = __uint_as_float((unsigned)a0) + __uint_as_float((unsigned)(a0 >> 32));
        float p1 = __uint_as_float((unsigned)a1) + __uint_as_float((unsigned)(a1 >> 32));
        sg[w][l] = p0 + p1;
        __syncthreads();

        if (tid < 32) {   // warp 0: cross-warp reduce + gates + publish
            float a = ((sg[0][l] + sg[1][l]) + (sg[2][l] + sg[3][l]))
                    + ((sg[4][l] + sg[5][l]) + (sg[6][l] + sg[7][l]));
            a += xv;
            float fg = __shfl_sync(0xffffffffu, a, (l & 7) + 8);
            float gg = __shfl_sync(0xffffffffu, a, (l & 7) + 16);
            float ov = __shfl_sync(0xffffffffu, a, (l & 7) + 24);
            if (l < 8) {
                float iv = 1.f / (1.f + expf(-a));
                fg = 1.f / (1.f + expf(-fg));
                gg = tanhf(gg);
                ov = 1.f / (1.f + expf(-ov));
                cst = fg * cst + iv * gg;
                float hn = ov * tanhf(cst);
                // release orders the sg reads above before the publish, so other
                // warps' next-step poll success implies sg is safe to overwrite.
                st_rel64(&g_hx[d][(s + 1) & 1][(r << 3) + l],
                         pack_ht(hn, (unsigned)(s + 2)));
                __stcg(&g_lstm[(size_t)t * 1024 + d * 512 + (r << 3) + l], hn);
            }
        }
        // no trailing __syncthreads: next-step poll provides the ordering.
    }
}

// ---------------- kernel 3: tag features -----------------------------------
__global__ void feats_k(const float* __restrict__ wtag, const float* __restrict__ btag)
{
    const int t = blockIdx.x;
    const int w = threadIdx.x >> 5;
    const int lane = threadIdx.x & 31;

    const float4* lx = (const float4*)(g_lstm + (size_t)t * 1024 + lane * 32);
    float4 X[8];
#pragma unroll
    for (int i = 0; i < 8; i++) X[i] = lx[i];

#pragma unroll
    for (int rep = 0; rep < 3; rep++) {
        int tag = w + rep * 8;
        const float4* wt = (const float4*)(wtag + (size_t)tag * 1024 + lane * 32);
        float a = 0.f;
#pragma unroll
        for (int i = 0; i < 8; i++) {
            float4 v = wt[i];
            a += X[i].x * v.x + X[i].y * v.y + X[i].z * v.z + X[i].w * v.w;
        }
#pragma unroll
        for (int o = 16; o; o >>= 1) a += __shfl_xor_sync(0xffffffffu, a, o);
        if (lane == 0) g_feats[t * TAGS + tag] = a + btag[tag];
    }
}

// ---------------- kernel 4: Viterbi (1 warp, bp in smem) -------------------
__global__ void viterbi_k(const float* __restrict__ trans, float* __restrict__ out,
                          int out_size)
{
    extern __shared__ unsigned char bp[];      // T_SEQ * TAGS bytes
    __shared__ float trs[TAGS * 25];
    __shared__ float stopr[TAGS];

    const int lane = threadIdx.x;
    for (int i = lane; i < TAGS * TAGS; i += 32) {
        int n = i / TAGS, p = i % TAGS;
        trs[n * 25 + p] = trans[i];
    }
    if (lane < TAGS) stopr[lane] = trans[STOP_T * TAGS + lane];
    __syncwarp();

    float fv = (lane == START_T) ? 0.f : NEGV;
    float feat = (lane < TAGS) ? g_feats[lane] : 0.f;

    for (int t = 0; t < T_SEQ; t++) {
        float nf = (lane < TAGS && t + 1 < T_SEQ) ? g_feats[(t + 1) * TAGS + lane] : 0.f;
        float best = -3.4e38f;
        int bi = 0;
#pragma unroll
        for (int p = 0; p < TAGS; p++) {
            float src = __shfl_sync(0xffffffffu, fv, p);
            float v = src + ((lane < TAGS) ? trs[lane * 25 + p] : 0.f);
            if (v > best) { best = v; bi = p; }
        }
        if (lane < TAGS) {
            fv = best + feat;
            bp[t * TAGS + lane] = (unsigned char)bi;
        } else {
            fv = NEGV;
        }
        feat = nf;
    }

    float ttl = (lane < TAGS) ? fv + stopr[lane] : -3.4e38f;
    float bv = ttl; int bi = lane;
#pragma unroll
    for (int o = 16; o; o >>= 1) {
        float ov = __shfl_down_sync(0xffffffffu, bv, o);
        int   oi = __shfl_down_sync(0xffffffffu, bi, o);
        if (ov > bv || (ov == bv && oi < bi)) { bv = ov; bi = oi; }
    }

    if (lane == 0) {
        float score = bv;
        int cur = bi;
        if (out_size >= T_SEQ + 1) {
            out[0] = score;
            float* path = out + 1;
            path[T_SEQ - 1] = (float)cur;
            for (int t = T_SEQ - 1; t >= 1; t--) {
                cur = bp[t * TAGS + cur];
                path[t - 1] = (float)cur;
            }
        } else if (out_size == T_SEQ) {
            out[T_SEQ - 1] = (float)cur;
            for (int t = T_SEQ - 1; t >= 1; t--) {
                cur = bp[t * TAGS + cur];
                out[t - 1] = (float)cur;
            }
        } else {
            out[0] = score;
        }
    }
}

// ---------------- launcher --------------------------------------------------
extern "C" void kernel_launch(void* const* d_in, const int* in_sizes, int n_in,
                              void* d_out, int out_size)
{
    const int*   sent  = (const int*)  d_in[0];
    const float* emb   = (const float*)d_in[1];
    const float* wihf  = (const float*)d_in[2];
    const float* whhf  = (const float*)d_in[3];
    const float* bihf  = (const float*)d_in[4];
    const float* bhhf  = (const float*)d_in[5];
    const float* wihb  = (const float*)d_in[6];
    const float* whhb  = (const float*)d_in[7];
    const float* bihb  = (const float*)d_in[8];
    const float* bhhb  = (const float*)d_in[9];
    const float* wtag  = (const float*)d_in[10];
    const float* btag  = (const float*)d_in[11];
    const float* trans = (const float*)d_in[12];
    const float* h0    = (const float*)d_in[13];
    const float* c0    = (const float*)d_in[14];
    float* out = (float*)d_out;

    proj_gemm<<<dim3(64, 64), 256>>>(sent, emb, wihf, wihb, bihf, bhhf, bihb, bhhb);
    lstm_rec<<<2 * NCTA_DIR, REC_THREADS>>>(whhf, whhb, h0, c0);
    feats_k<<<T_SEQ, 256>>>(wtag, btag);

    cudaFuncSetAttribute(viterbi_k, cudaFuncAttributeMaxDynamicSharedMemorySize,
                         T_SEQ * TAGS);
    viterbi_k<<<1, 32, T_SEQ * TAGS>>>(trans, out, out_size);
}

// round 11
// speedup vs baseline: 1.4967x; 1.0909x over previous
#include <cuda_runtime.h>
#include <cstdint>
#include <cmath>

#define T_SEQ   4096
#define TAGS    24
#define START_T 22
#define STOP_T  23
#define NEGV    (-10000.0f)

#define NCTA_DIR    64
#define REC_THREADS 256

// ---------------- scratch (device globals; no cudaMalloc allowed) ----------
__device__ float    g_xg[(size_t)T_SEQ * 4096];   // [t][dir*2048 + gate*512 + cell]
__device__ float    g_lstm[(size_t)T_SEQ * 1024]; // [t][dir*512 + cell]
__device__ float    g_feats[T_SEQ * TAGS];
// h exchange: one 8B word per cell = (tag<<32 | fp32 bits). Tag==step+1 for the
// h that is INPUT to step 'step'; double-buffered by step parity.
__device__ unsigned long long g_hx[2][2][512];    // [dir][parity][cell]

__device__ __forceinline__ unsigned long long ld_acq64(const unsigned long long* p)
{
    unsigned long long v;
    asm volatile("ld.acquire.gpu.global.u64 %0, [%1];" : "=l"(v) : "l"(p) : "memory");
    return v;
}
__device__ __forceinline__ void st_rel64(unsigned long long* p, unsigned long long v)
{
    asm volatile("st.release.gpu.global.u64 [%0], %1;" :: "l"(p), "l"(v) : "memory");
}
__device__ __forceinline__ unsigned long long pack_ht(float h, unsigned tag)
{
    return ((unsigned long long)tag << 32) | (unsigned long long)__float_as_uint(h);
}

#define FMA2(d, a, b, c) \
    asm("fma.rn.f32x2 %0, %1, %2, %3;" : "=l"(d) : "l"(a), "l"(b), "l"(c))

// ---------------- kernel 1: fused gather + input-projection GEMM -----------
__global__ void proj_gemm(const int* __restrict__ sent, const float* __restrict__ emb,
                          const float* __restrict__ wf, const float* __restrict__ wb,
                          const float* __restrict__ bihf, const float* __restrict__ bhhf,
                          const float* __restrict__ bihb, const float* __restrict__ bhhb)
{
    __shared__ __align__(16) float As[32][68];
    __shared__ __align__(16) float Bs[32][68];
    __shared__ int toks[64];

    const int tid = threadIdx.x;          // 0..255
    const int m0 = blockIdx.y * 64;
    const int n0 = blockIdx.x * 64;
    if (tid < 64) toks[tid] = sent[m0 + tid];
    __syncthreads();

    const int ty = tid >> 4;
    const int tx = tid & 15;

    float acc[4][4];
#pragma unroll
    for (int i = 0; i < 4; i++)
#pragma unroll
        for (int j = 0; j < 4; j++) acc[i][j] = 0.f;

    for (int k0 = 0; k0 < 512; k0 += 32) {
#pragma unroll
        for (int r = 0; r < 2; r++) {
            int idx = tid + r * 256;
            int row = idx >> 3;
            int kq  = idx & 7;
            float4 a = *(const float4*)(emb + (size_t)toks[row] * 512 + k0 + kq * 4);
            As[kq*4+0][row] = a.x; As[kq*4+1][row] = a.y;
            As[kq*4+2][row] = a.z; As[kq*4+3][row] = a.w;
            int n = n0 + row;
            const float* wsrc = (n < 2048) ? (wf + (size_t)n * 512)
                                           : (wb + (size_t)(n - 2048) * 512);
            float4 b = *(const float4*)(wsrc + k0 + kq * 4);
            Bs[kq*4+0][row] = b.x; Bs[kq*4+1][row] = b.y;
            Bs[kq*4+2][row] = b.z; Bs[kq*4+3][row] = b.w;
        }
        __syncthreads();
#pragma unroll
        for (int kk = 0; kk < 32; kk++) {
            float4 aa = *(const float4*)&As[kk][ty * 4];
            float4 bb = *(const float4*)&Bs[kk][tx * 4];
            float av[4] = {aa.x, aa.y, aa.z, aa.w};
            float bv[4] = {bb.x, bb.y, bb.z, bb.w};
#pragma unroll
            for (int i = 0; i < 4; i++)
#pragma unroll
                for (int j = 0; j < 4; j++) acc[i][j] += av[i] * bv[j];
        }
        __syncthreads();
    }

#pragma unroll
    for (int i = 0; i < 4; i++) {
        int m = m0 + ty * 4 + i;
        float* orow = g_xg + (size_t)m * 4096 + n0 + tx * 4;
#pragma unroll
        for (int j = 0; j < 4; j++) {
            int n = n0 + tx * 4 + j;
            float bias = (n < 2048) ? (bihf[n] + bhhf[n])
                                    : (bihb[n - 2048] + bhhb[n - 2048]);
            orow[j] = acc[i][j] + bias;
        }
    }
}

// ---------------- kernel 2: persistent BiLSTM recurrence -------------------
// 128 CTAs (64/dir), 256 threads. Thread (w=tid>>5, l=tid&31):
//   gate-row = (l>>3)*512 + 8r + (l&7), k-slice [64w, 64w+64), weights packed
//   as f32x2 in REGISTERS. h published per cell as (tag|value) 8B words:
//   the successful acquire-poll IS the data transfer (one L2 round trip).
__global__ void __launch_bounds__(REC_THREADS, 1)
lstm_rec(const float* __restrict__ whf, const float* __restrict__ whb,
         const float* __restrict__ h0, const float* __restrict__ c0)
{
    const int cta = blockIdx.x;       // 0..127
    const int d   = cta >> 6;
    const int r   = cta & 63;         // owns cells [8r, 8r+8)
    const int tid = threadIdx.x;
    const int w   = tid >> 5;         // 0..7 k-slice (warp-uniform)
    const int l   = tid & 31;         // 0..31 local gate-row
    const int gate = l >> 3;
    const int cell = (r << 3) + (l & 7);
    const int row  = gate * 512 + cell;

    const float* whh = d ? whb : whf;

    // ---- weights -> registers, packed f32x2 (one-time) ----
    unsigned long long W2[32];
    {
        const float2* wp = (const float2*)(whh + (size_t)row * 512 + w * 64);
#pragma unroll
        for (int i = 0; i < 32; i++) {
            float2 v = wp[i];
            W2[i] = ((unsigned long long)__float_as_uint(v.y) << 32)
                  | (unsigned long long)__float_as_uint(v.x);
        }
    }

    __shared__ __align__(16) float hsh[8][64];  // per-warp h slice
    __shared__ float sg[8][33];                 // [w][l] partials, padded

    float cst = 0.f;
    if (tid < 8) {
        cst = c0[d * 512 + (r << 3) + tid];
        st_rel64(&g_hx[d][0][(r << 3) + tid],
                 pack_ht(h0[d * 512 + (r << 3) + tid], 1u));
    }

    for (int s = 0; s < T_SEQ; s++) {
        const int t = d ? (T_SEQ - 1 - s) : s;

        // xg prefetch for reducer lanes (independent of h)
        float xv = 0.f;
        if (tid < 32) xv = __ldcg(&g_xg[(size_t)t * 4096 + d * 2048 + row]);

        // ---- poll h (data-embedded tags); poll success == data arrival ----
        const unsigned want = (unsigned)(s + 1);
        const unsigned long long* hb = &g_hx[d][s & 1][w * 64];
        unsigned long long v0 = 0, v1 = 0;
        bool d0 = false, d1 = false;
        for (;;) {
            if (!d0) { v0 = ld_acq64(hb + l);      d0 = ((unsigned)(v0 >> 32) == want); }
            if (!d1) { v1 = ld_acq64(hb + 32 + l); d1 = ((unsigned)(v1 >> 32) == want); }
            if (__all_sync(0xffffffffu, d0 && d1)) break;
        }
        hsh[w][l]      = __uint_as_float((unsigned)v0);
        hsh[w][32 + l] = __uint_as_float((unsigned)v1);
        __syncwarp();

        // ---- dot: packed f32x2 FMA over warp's 64-wide k-slice ----
        const ulonglong2* hv = (const ulonglong2*)&hsh[w][0];  // 16 × 16B, broadcast LDS
        unsigned long long a0 = 0ull, a1 = 0ull;
#pragma unroll
        for (int i = 0; i < 16; i++) {
            ulonglong2 h2 = hv[i];
            FMA2(a0, W2[2 * i],     h2.x, a0);
            FMA2(a1, W2[2 * i + 1], h2.y, a1);
        }
        float p0 = __uint_as_float((unsigned)a0) + __uint_as_float((unsigned)(a0 >> 32));
        float p1 = __uint_as_float((unsigned)a1) + __uint_as_float((unsigned)(a1 >> 32));
        sg[w][l] = p0 + p1;
        __syncthreads();

        if (tid < 32) {   // warp 0: cross-warp reduce + gates + publish
            float a = ((sg[0][l] + sg[1][l]) + (sg[2][l] + sg[3][l]))
                    + ((sg[4][l] + sg[5][l]) + (sg[6][l] + sg[7][l]));
            a += xv;
            float fg = __shfl_sync(0xffffffffu, a, (l & 7) + 8);
            float gg = __shfl_sync(0xffffffffu, a, (l & 7) + 16);
            float ov = __shfl_sync(0xffffffffu, a, (l & 7) + 24);
            if (l < 8) {
                float iv = 1.f / (1.f + expf(-a));
                fg = 1.f / (1.f + expf(-fg));
                gg = tanhf(gg);
                ov = 1.f / (1.f + expf(-ov));
                cst = fg * cst + iv * gg;
                float hn = ov * tanhf(cst);
                // release orders the sg reads above before the publish, so other
                // warps' next-step poll success implies sg is safe to overwrite.
                st_rel64(&g_hx[d][(s + 1) & 1][(r << 3) + l],
                         pack_ht(hn, (unsigned)(s + 2)));
                __stcg(&g_lstm[(size_t)t * 1024 + d * 512 + (r << 3) + l], hn);
            }
        }
        // no trailing __syncthreads: next-step poll provides the ordering.
    }
}

// ---------------- kernel 3: tag features -----------------------------------
__global__ void feats_k(const float* __restrict__ wtag, const float* __restrict__ btag)
{
    const int t = blockIdx.x;
    const int w = threadIdx.x >> 5;
    const int lane = threadIdx.x & 31;

    const float4* lx = (const float4*)(g_lstm + (size_t)t * 1024 + lane * 32);
    float4 X[8];
#pragma unroll
    for (int i = 0; i < 8; i++) X[i] = lx[i];

#pragma unroll
    for (int rep = 0; rep < 3; rep++) {
        int tag = w + rep * 8;
        const float4* wt = (const float4*)(wtag + (size_t)tag * 1024 + lane * 32);
        float a = 0.f;
#pragma unroll
        for (int i = 0; i < 8; i++) {
            float4 v = wt[i];
            a += X[i].x * v.x + X[i].y * v.y + X[i].z * v.z + X[i].w * v.w;
        }
#pragma unroll
        for (int o = 16; o; o >>= 1) a += __shfl_xor_sync(0xffffffffu, a, o);
        if (lane == 0) g_feats[t * TAGS + tag] = a + btag[tag];
    }
}

// ---------------- kernel 4: Viterbi (1 warp, bp in smem) -------------------
__global__ void viterbi_k(const float* __restrict__ trans, float* __restrict__ out,
                          int out_size)
{
    extern __shared__ unsigned char bp[];      // T_SEQ * TAGS bytes
    __shared__ float trs[TAGS * 25];
    __shared__ float stopr[TAGS];

    const int lane = threadIdx.x;
    for (int i = lane; i < TAGS * TAGS; i += 32) {
        int n = i / TAGS, p = i % TAGS;
        trs[n * 25 + p] = trans[i];
    }
    if (lane < TAGS) stopr[lane] = trans[STOP_T * TAGS + lane];
    __syncwarp();

    float fv = (lane == START_T) ? 0.f : NEGV;
    float feat = (lane < TAGS) ? g_feats[lane] : 0.f;

    for (int t = 0; t < T_SEQ; t++) {
        float nf = (lane < TAGS && t + 1 < T_SEQ) ? g_feats[(t + 1) * TAGS + lane] : 0.f;
        float best = -3.4e38f;
        int bi = 0;
#pragma unroll
        for (int p = 0; p < TAGS; p++) {
            float src = __shfl_sync(0xffffffffu, fv, p);
            float v = src + ((lane < TAGS) ? trs[lane * 25 + p] : 0.f);
            if (v > best) { best = v; bi = p; }
        }
        if (lane < TAGS) {
            fv = best + feat;
            bp[t * TAGS + lane] = (unsigned char)bi;
        } else {
            fv = NEGV;
        }
        feat = nf;
    }

    float ttl = (lane < TAGS) ? fv + stopr[lane] : -3.4e38f;
    float bv = ttl; int bi = lane;
#pragma unroll
    for (int o = 16; o; o >>= 1) {
        float ov = __shfl_down_sync(0xffffffffu, bv, o);
        int   oi = __shfl_down_sync(0xffffffffu, bi, o);
        if (ov > bv || (ov == bv && oi < bi)) { bv = ov; bi = oi; }
    }

    if (lane == 0) {
        float score = bv;
        int cur = bi;
        if (out_size >= T_SEQ + 1) {
            out[0] = score;
            float* path = out + 1;
            path[T_SEQ - 1] = (float)cur;
            for (int t = T_SEQ - 1; t >= 1; t--) {
                cur = bp[t * TAGS + cur];
                path[t - 1] = (float)cur;
            }
        } else if (out_size == T_SEQ) {
            out[T_SEQ - 1] = (float)cur;
            for (int t = T_SEQ - 1; t >= 1; t--) {
                cur = bp[t * TAGS + cur];
                out[t - 1] = (float)cur;
            }
        } else {
            out[0] = score;
        }
    }
}

// ---------------- launcher --------------------------------------------------
extern "C" void kernel_launch(void* const* d_in, const int* in_sizes, int n_in,
                              void* d_out, int out_size)
{
    const int*   sent  = (const int*)  d_in[0];
    const float* emb   = (const float*)d_in[1];
    const float* wihf  = (const float*)d_in[2];
    const float* whhf  = (const float*)d_in[3];
    const float* bihf  = (const float*)d_in[4];
    const float* bhhf  = (const float*)d_in[5];
    const float* wihb  = (const float*)d_in[6];
    const float* whhb  = (const float*)d_in[7];
    const float* bihb  = (const float*)d_in[8];
    const float* bhhb  = (const float*)d_in[9];
    const float* wtag  = (const float*)d_in[10];
    const float* btag  = (const float*)d_in[11];
    const float* trans = (const float*)d_in[12];
    const float* h0    = (const float*)d_in[13];
    const float* c0    = (const float*)d_in[14];
    float* out = (float*)d_out;

    proj_gemm<<<dim3(64, 64), 256>>>(sent, emb, wihf, wihb, bihf, bhhf, bihb, bhhb);
    lstm_rec<<<2 * NCTA_DIR, REC_THREADS>>>(whhf, whhb, h0, c0);
    feats_k<<<T_SEQ, 256>>>(wtag, btag);

    cudaFuncSetAttribute(viterbi_k, cudaFuncAttributeMaxDynamicSharedMemorySize,
                         T_SEQ * TAGS);
    viterbi_k<<<1, 32, T_SEQ * TAGS>>>(trans, out, out_size);
}